// round 13
// baseline (speedup 1.0000x reference)
#include <cuda_runtime.h>
#include <cuda_bf16.h>

#define Bb 8
#define Cc 256
#define Hh 224
#define Ww 224
#define HW (Hh * Ww)              // 50176
#define PIX2 512                  // pixels per K1 block (128 float4 groups)
#define NCH2 (HW / PIX2)          // 98 chunks per batch
#define CGRP 7                    // chunks per K2a block (98 = 14*7)
#define NGRP (NCH2 / CGRP)        // 14
#define RSEG 14                   // rows per thread in K3
#define NSEG 4
#define RS (RSEG * NSEG)          // 56 rows per K3 block

// Scratch (__device__ globals: allocation-free)
__device__ float g_partial[NCH2 * Bb * Cc];  // per-block channel partials
__device__ float g_p2[NGRP * Bb * Cc];       // stage-2 partials
__device__ float g_S[Bb * HW];               // sigmoided spatial gate
__device__ float g_ch[Bb * Cc];              // sigmoided channel gate

// sigmoid(v) = 0.5*tanh(0.5*v) + 0.5 — HW MUFU.TANH. |err| ~ 2^-12.
__device__ __forceinline__ float fsigmoid(float v) {
    float t;
    asm("tanh.approx.f32 %0, %1;" : "=f"(t) : "f"(v * 0.5f));
    return fmaf(0.5f, t, 0.5f);
}

// ---------------------------------------------------------------------------
// K1 (67.4us, at its DRAM floor): in-block channel split, gate written
// directly, one coalesced 256-float channel partial per block.
// grid = (NCH2, B), block = 256.
// ---------------------------------------------------------------------------
__global__ __launch_bounds__(256) void k1_spatial_and_sums(
    const float* __restrict__ x,
    const float* __restrict__ spatial_w,
    const float* __restrict__ spatial_b)
{
    __shared__ float s_w[Cc];
    __shared__ float sdot[4][128];
    __shared__ float s_wsum[8][128];

    const int tid  = threadIdx.x;
    const int warp = tid >> 5;
    const int lane = tid & 31;
    const int half = warp >> 2;
    const int t    = tid & 127;
    const int chunk = blockIdx.x;
    const int b     = blockIdx.y;

    s_w[tid] = spatial_w[tid];
    __syncthreads();

    const float4* xb = reinterpret_cast<const float4*>(
        x + (size_t)b * Cc * HW + (size_t)chunk * PIX2);
    const int cs4 = HW / 4;
    const int cbase = half * 128;

    float d0 = 0.f, d1 = 0.f, d2 = 0.f, d3 = 0.f;

    #pragma unroll 16
    for (int c = 0; c < 128; ++c) {
        float4 v = __ldg(&xb[(size_t)(cbase + c) * cs4 + t]);
        float wv = s_w[cbase + c];
        d0 = fmaf(v.x, wv, d0);
        d1 = fmaf(v.y, wv, d1);
        d2 = fmaf(v.z, wv, d2);
        d3 = fmaf(v.w, wv, d3);
        float cs = (v.x + v.y) + (v.z + v.w);
        cs += __shfl_down_sync(0xFFFFFFFFu, cs, 16);
        cs += __shfl_down_sync(0xFFFFFFFFu, cs, 8);
        cs += __shfl_down_sync(0xFFFFFFFFu, cs, 4);
        cs += __shfl_down_sync(0xFFFFFFFFu, cs, 2);
        cs += __shfl_down_sync(0xFFFFFFFFu, cs, 1);
        if (lane == 0) s_wsum[warp][c] = cs;
    }

    if (half == 0) {
        sdot[0][t] = d0; sdot[1][t] = d1; sdot[2][t] = d2; sdot[3][t] = d3;
    }
    __syncthreads();

    {
        float s = s_wsum[half * 4 + 0][t] + s_wsum[half * 4 + 1][t]
                + s_wsum[half * 4 + 2][t] + s_wsum[half * 4 + 3][t];
        g_partial[((size_t)chunk * Bb + b) * Cc + tid] = s;
    }

    if (half == 1) {
        const float sb = spatial_b[0];
        float4 g;
        g.x = fsigmoid(d0 + sdot[0][t] + sb);
        g.y = fsigmoid(d1 + sdot[1][t] + sb);
        g.z = fsigmoid(d2 + sdot[2][t] + sb);
        g.w = fsigmoid(d3 + sdot[3][t] + sb);
        reinterpret_cast<float4*>(g_S + (size_t)b * HW + (size_t)chunk * PIX2)[t] = g;
    }
}

// ---------------------------------------------------------------------------
// K2a: parallel stage of the channel-sum reduce (112 blocks, coalesced).
// grid = (NGRP, B), block = 256
// ---------------------------------------------------------------------------
__global__ __launch_bounds__(256) void k2a_reduce(void)
{
    const int cg  = blockIdx.x;
    const int b   = blockIdx.y;
    const int tid = threadIdx.x;

    float s = 0.f;
    #pragma unroll
    for (int j = 0; j < CGRP; ++j)
        s += g_partial[((size_t)(cg * CGRP + j) * Bb + b) * Cc + tid];
    g_p2[((size_t)cg * Bb + b) * Cc + tid] = s;
}

// ---------------------------------------------------------------------------
// K2b: final reduce (14 partials) -> avg -> MLP -> channel gate.
// grid = B, block = 256
// ---------------------------------------------------------------------------
__global__ __launch_bounds__(256) void k2b_channel_gate(
    const float* __restrict__ cc1_w,
    const float* __restrict__ cc1_b,
    const float* __restrict__ cc2_w,
    const float* __restrict__ cc2_b)
{
    __shared__ float s_avg[Cc];
    __shared__ float s_hid[Cc / 4];

    const int b   = blockIdx.x;
    const int tid = threadIdx.x;

    float s = 0.f;
    #pragma unroll
    for (int cg = 0; cg < NGRP; ++cg)
        s += g_p2[((size_t)cg * Bb + b) * Cc + tid];
    s_avg[tid] = s * (1.0f / (float)HW);
    __syncthreads();

    if (tid < Cc / 4) {
        float acc = cc1_b[tid];
        const float* wrow = cc1_w + tid * Cc;
        #pragma unroll 4
        for (int c = 0; c < Cc; ++c) acc = fmaf(s_avg[c], wrow[c], acc);
        s_hid[tid] = fmaxf(acc, 0.f);
    }
    __syncthreads();

    float acc = cc2_b[tid];
    const float* wrow = cc2_w + tid * (Cc / 4);
    #pragma unroll
    for (int j = 0; j < Cc / 4; ++j) acc = fmaf(s_hid[j], wrow[j], acc);
    g_ch[b * Cc + tid] = fsigmoid(acc);
}

// ---------------------------------------------------------------------------
// K3 v4: vectorized 3x3 box stencil + fused gating, RSEG=14 fully unrolled,
// scalar L1-hit halo loads, HW-tanh sigmoid, and a one-iteration software
// prefetch of the next x row so the DRAM load issues a full iteration before
// its use. __launch_bounds__(224, 5) relaxes the reg budget (<=58) so ptxas
// can keep more loads in flight.
// grid = (4, B*C), block = 224 (56 col-groups x 4 row-segments)
// ---------------------------------------------------------------------------
__global__ __launch_bounds__(224, 5) void k3_edge_and_gate(
    const float* __restrict__ x,
    float* __restrict__ out)
{
    const int t   = threadIdx.x;
    const int c4  = t % 56;            // float4 column group 0..55
    const int seg = t / 56;            // row segment 0..3
    const int col = c4 * 4;

    const int plane = blockIdx.y;      // b*C + c
    const int b     = plane >> 8;
    const int rst   = blockIdx.x * RS + seg * RSEG;

    const float* xp = x + (size_t)plane * HW;

    auto ldrow = [&](int r, float& lf, float& rf) -> float4 {
        if ((unsigned)r >= (unsigned)Hh) {
            lf = 0.f; rf = 0.f;
            return make_float4(0.f, 0.f, 0.f, 0.f);
        }
        const float* row = xp + r * Ww;
        float4 v = __ldg(reinterpret_cast<const float4*>(row + col));
        lf = (c4 > 0)  ? __ldg(row + col - 1) : 0.f;
        rf = (c4 < 55) ? __ldg(row + col + 4) : 0.f;
        return v;
    };
    auto hs = [](float4 v, float l, float r) -> float4 {
        float t1 = v.x + v.y;
        float t2 = v.z + v.w;
        return make_float4(l + t1, t1 + v.z, v.y + t2, t2 + r);
    };

    float lf, rf;
    float4 vA = ldrow(rst - 1, lf, rf);
    float4 hm = hs(vA, lf, rf);
    float4 vc = ldrow(rst, lf, rf);
    float4 hc = hs(vc, lf, rf);

    // prefetched next row (raw, halos kept separate so hs happens at use)
    float lfP, rfP;
    float4 vP = ldrow(rst + 1, lfP, rfP);

    const float K = __ldg(&g_ch[plane]);
    const float* gSp = g_S + (size_t)b * HW + (size_t)rst * Ww + col;
    float*       op  = out + (size_t)plane * HW + (size_t)rst * Ww + col;

    #pragma unroll
    for (int i = 0; i < RSEG; ++i) {
        // consume prefetched row, immediately issue the next one
        float4 vp = vP;
        float  lfc = lfP, rfc = rfP;
        vP = ldrow(rst + i + 2, lfP, rfP);   // guarded: returns zeros past H

        float4 sg = __ldg(reinterpret_cast<const float4*>(gSp + i * Ww));
        float4 hp = hs(vp, lfc, rfc);

        float4 o;
        o.x = vc.x * (sg.x * K * fsigmoid(fmaf(9.f, vc.x, -((hm.x + hc.x) + hp.x))));
        o.y = vc.y * (sg.y * K * fsigmoid(fmaf(9.f, vc.y, -((hm.y + hc.y) + hp.y))));
        o.z = vc.z * (sg.z * K * fsigmoid(fmaf(9.f, vc.z, -((hm.z + hc.z) + hp.z))));
        o.w = vc.w * (sg.w * K * fsigmoid(fmaf(9.f, vc.w, -((hm.w + hc.w) + hp.w))));
        *reinterpret_cast<float4*>(op + i * Ww) = o;

        hm = hc; hc = hp; vc = vp;
    }
}

// ---------------------------------------------------------------------------
extern "C" void kernel_launch(void* const* d_in, const int* in_sizes, int n_in,
                              void* d_out, int out_size)
{
    const float* x         = (const float*)d_in[0];
    const float* spatial_w = (const float*)d_in[1];
    const float* spatial_b = (const float*)d_in[2];
    const float* cc1_w     = (const float*)d_in[3];
    const float* cc1_b     = (const float*)d_in[4];
    const float* cc2_w     = (const float*)d_in[5];
    const float* cc2_b     = (const float*)d_in[6];
    float* out             = (float*)d_out;

    dim3 g1(NCH2, Bb);
    k1_spatial_and_sums<<<g1, 256>>>(x, spatial_w, spatial_b);

    dim3 g2a(NGRP, Bb);
    k2a_reduce<<<g2a, 256>>>();

    k2b_channel_gate<<<Bb, 256>>>(cc1_w, cc1_b, cc2_w, cc2_b);

    dim3 g3(Hh / RS, Bb * Cc);
    k3_edge_and_gate<<<g3, 224>>>(x, out);
}

// round 14
// speedup vs baseline: 1.0056x; 1.0056x over previous
#include <cuda_runtime.h>
#include <cuda_bf16.h>

#define Bb 8
#define Cc 256
#define Hh 224
#define Ww 224
#define HW (Hh * Ww)              // 50176
#define PIX2 512                  // pixels per K1 block (128 float4 groups)
#define NCH2 (HW / PIX2)          // 98 chunks per batch
#define CGRP 7                    // chunks per K2a block (98 = 14*7)
#define NGRP (NCH2 / CGRP)        // 14
#define RSEG 14                   // rows per thread in K3
#define NSEG 4
#define RS (RSEG * NSEG)          // 56 rows per K3 block

// Scratch (__device__ globals: allocation-free)
__device__ float g_partial[NCH2 * Bb * Cc];  // per-block channel partials
__device__ float g_p2[NGRP * Bb * Cc];       // stage-2 partials
__device__ float g_S[Bb * HW];               // sigmoided spatial gate
__device__ float g_ch[Bb * Cc];              // sigmoided channel gate

// sigmoid(v) = 0.5*tanh(0.5*v) + 0.5 — HW MUFU.TANH. |err| ~ 2^-12.
__device__ __forceinline__ float fsigmoid(float v) {
    float t;
    asm("tanh.approx.f32 %0, %1;" : "=f"(t) : "f"(v * 0.5f));
    return fmaf(0.5f, t, 0.5f);
}

// ---------------------------------------------------------------------------
// K1 (67.4us, at its DRAM floor): in-block channel split, gate written
// directly, one coalesced 256-float channel partial per block.
// grid = (NCH2, B), block = 256.
// ---------------------------------------------------------------------------
__global__ __launch_bounds__(256) void k1_spatial_and_sums(
    const float* __restrict__ x,
    const float* __restrict__ spatial_w,
    const float* __restrict__ spatial_b)
{
    __shared__ float s_w[Cc];
    __shared__ float sdot[4][128];
    __shared__ float s_wsum[8][128];

    const int tid  = threadIdx.x;
    const int warp = tid >> 5;
    const int lane = tid & 31;
    const int half = warp >> 2;
    const int t    = tid & 127;
    const int chunk = blockIdx.x;
    const int b     = blockIdx.y;

    s_w[tid] = spatial_w[tid];
    __syncthreads();

    const float4* xb = reinterpret_cast<const float4*>(
        x + (size_t)b * Cc * HW + (size_t)chunk * PIX2);
    const int cs4 = HW / 4;
    const int cbase = half * 128;

    float d0 = 0.f, d1 = 0.f, d2 = 0.f, d3 = 0.f;

    #pragma unroll 16
    for (int c = 0; c < 128; ++c) {
        float4 v = __ldg(&xb[(size_t)(cbase + c) * cs4 + t]);
        float wv = s_w[cbase + c];
        d0 = fmaf(v.x, wv, d0);
        d1 = fmaf(v.y, wv, d1);
        d2 = fmaf(v.z, wv, d2);
        d3 = fmaf(v.w, wv, d3);
        float cs = (v.x + v.y) + (v.z + v.w);
        cs += __shfl_down_sync(0xFFFFFFFFu, cs, 16);
        cs += __shfl_down_sync(0xFFFFFFFFu, cs, 8);
        cs += __shfl_down_sync(0xFFFFFFFFu, cs, 4);
        cs += __shfl_down_sync(0xFFFFFFFFu, cs, 2);
        cs += __shfl_down_sync(0xFFFFFFFFu, cs, 1);
        if (lane == 0) s_wsum[warp][c] = cs;
    }

    if (half == 0) {
        sdot[0][t] = d0; sdot[1][t] = d1; sdot[2][t] = d2; sdot[3][t] = d3;
    }
    __syncthreads();

    {
        float s = s_wsum[half * 4 + 0][t] + s_wsum[half * 4 + 1][t]
                + s_wsum[half * 4 + 2][t] + s_wsum[half * 4 + 3][t];
        g_partial[((size_t)chunk * Bb + b) * Cc + tid] = s;
    }

    if (half == 1) {
        const float sb = spatial_b[0];
        float4 g;
        g.x = fsigmoid(d0 + sdot[0][t] + sb);
        g.y = fsigmoid(d1 + sdot[1][t] + sb);
        g.z = fsigmoid(d2 + sdot[2][t] + sb);
        g.w = fsigmoid(d3 + sdot[3][t] + sb);
        reinterpret_cast<float4*>(g_S + (size_t)b * HW + (size_t)chunk * PIX2)[t] = g;
    }
}

// ---------------------------------------------------------------------------
// K2a: parallel stage of the channel-sum reduce (112 blocks, coalesced).
// grid = (NGRP, B), block = 256
// ---------------------------------------------------------------------------
__global__ __launch_bounds__(256) void k2a_reduce(void)
{
    const int cg  = blockIdx.x;
    const int b   = blockIdx.y;
    const int tid = threadIdx.x;

    float s = 0.f;
    #pragma unroll
    for (int j = 0; j < CGRP; ++j)
        s += g_partial[((size_t)(cg * CGRP + j) * Bb + b) * Cc + tid];
    g_p2[((size_t)cg * Bb + b) * Cc + tid] = s;
}

// ---------------------------------------------------------------------------
// K2b: final reduce (14 partials) -> avg -> MLP -> channel gate.
// grid = B, block = 256
// ---------------------------------------------------------------------------
__global__ __launch_bounds__(256) void k2b_channel_gate(
    const float* __restrict__ cc1_w,
    const float* __restrict__ cc1_b,
    const float* __restrict__ cc2_w,
    const float* __restrict__ cc2_b)
{
    __shared__ float s_avg[Cc];
    __shared__ float s_hid[Cc / 4];

    const int b   = blockIdx.x;
    const int tid = threadIdx.x;

    float s = 0.f;
    #pragma unroll
    for (int cg = 0; cg < NGRP; ++cg)
        s += g_p2[((size_t)cg * Bb + b) * Cc + tid];
    s_avg[tid] = s * (1.0f / (float)HW);
    __syncthreads();

    if (tid < Cc / 4) {
        float acc = cc1_b[tid];
        const float* wrow = cc1_w + tid * Cc;
        #pragma unroll 4
        for (int c = 0; c < Cc; ++c) acc = fmaf(s_avg[c], wrow[c], acc);
        s_hid[tid] = fmaxf(acc, 0.f);
    }
    __syncthreads();

    float acc = cc2_b[tid];
    const float* wrow = cc2_w + tid * (Cc / 4);
    #pragma unroll
    for (int j = 0; j < Cc / 4; ++j) acc = fmaf(s_hid[j], wrow[j], acc);
    g_ch[b * Cc + tid] = fsigmoid(acc);
}

// ---------------------------------------------------------------------------
// K3 (R11 body + streaming stores): vectorized 3x3 box stencil + fused
// gating, RSEG=14 fully unrolled, scalar L1-hit halo loads, HW-tanh sigmoid.
// Output written with __stwt (write-through / evict-first): out is never
// re-read, so don't let 411MB of dead lines churn L2.
// grid = (4, B*C), block = 224 (56 col-groups x 4 row-segments)
// ---------------------------------------------------------------------------
__global__ __launch_bounds__(224) void k3_edge_and_gate(
    const float* __restrict__ x,
    float* __restrict__ out)
{
    const int t   = threadIdx.x;
    const int c4  = t % 56;            // float4 column group 0..55
    const int seg = t / 56;            // row segment 0..3
    const int col = c4 * 4;

    const int plane = blockIdx.y;      // b*C + c
    const int b     = plane >> 8;
    const int rst   = blockIdx.x * RS + seg * RSEG;

    const float* xp = x + (size_t)plane * HW;

    auto ldrow = [&](int r, float& lf, float& rf) -> float4 {
        if ((unsigned)r >= (unsigned)Hh) {
            lf = 0.f; rf = 0.f;
            return make_float4(0.f, 0.f, 0.f, 0.f);
        }
        const float* row = xp + r * Ww;
        float4 v = __ldg(reinterpret_cast<const float4*>(row + col));
        lf = (c4 > 0)  ? __ldg(row + col - 1) : 0.f;
        rf = (c4 < 55) ? __ldg(row + col + 4) : 0.f;
        return v;
    };
    auto hs = [](float4 v, float l, float r) -> float4 {
        float t1 = v.x + v.y;
        float t2 = v.z + v.w;
        return make_float4(l + t1, t1 + v.z, v.y + t2, t2 + r);
    };

    float lf, rf;
    float4 vA = ldrow(rst - 1, lf, rf);
    float4 hm = hs(vA, lf, rf);
    float4 vc = ldrow(rst, lf, rf);
    float4 hc = hs(vc, lf, rf);

    const float K = __ldg(&g_ch[plane]);
    const float* gSp = g_S + (size_t)b * HW + (size_t)rst * Ww + col;
    float*       op  = out + (size_t)plane * HW + (size_t)rst * Ww + col;

    #pragma unroll
    for (int i = 0; i < RSEG; ++i) {
        float4 vp = ldrow(rst + i + 1, lf, rf);
        float4 hp = hs(vp, lf, rf);
        float4 sg = __ldg(reinterpret_cast<const float4*>(gSp + i * Ww));

        float4 o;
        o.x = vc.x * (sg.x * K * fsigmoid(fmaf(9.f, vc.x, -((hm.x + hc.x) + hp.x))));
        o.y = vc.y * (sg.y * K * fsigmoid(fmaf(9.f, vc.y, -((hm.y + hc.y) + hp.y))));
        o.z = vc.z * (sg.z * K * fsigmoid(fmaf(9.f, vc.z, -((hm.z + hc.z) + hp.z))));
        o.w = vc.w * (sg.w * K * fsigmoid(fmaf(9.f, vc.w, -((hm.w + hc.w) + hp.w))));
        __stwt(reinterpret_cast<float4*>(op + i * Ww), o);

        hm = hc; hc = hp; vc = vp;
    }
}

// ---------------------------------------------------------------------------
extern "C" void kernel_launch(void* const* d_in, const int* in_sizes, int n_in,
                              void* d_out, int out_size)
{
    const float* x         = (const float*)d_in[0];
    const float* spatial_w = (const float*)d_in[1];
    const float* spatial_b = (const float*)d_in[2];
    const float* cc1_w     = (const float*)d_in[3];
    const float* cc1_b     = (const float*)d_in[4];
    const float* cc2_w     = (const float*)d_in[5];
    const float* cc2_b     = (const float*)d_in[6];
    float* out             = (float*)d_out;

    dim3 g1(NCH2, Bb);
    k1_spatial_and_sums<<<g1, 256>>>(x, spatial_w, spatial_b);

    dim3 g2a(NGRP, Bb);
    k2a_reduce<<<g2a, 256>>>();

    k2b_channel_gate<<<Bb, 256>>>(cc1_w, cc1_b, cc2_w, cc2_b);

    dim3 g3(Hh / RS, Bb * Cc);
    k3_edge_and_gate<<<g3, 224>>>(x, out);
}